// round 5
// baseline (speedup 1.0000x reference)
#include <cuda_runtime.h>
#include <math.h>

#define BB 4
#define CC 256
#define OO 256
#define KK 2304          // C * 9
#define NPIX 16384
#define PT 32            // pixels per block (one row segment, same h, same b)
#define ROW 260          // offset-phase sv row stride (floats)

// Static device scratch
__device__ float g_xT[BB * 4096 * CC];      // [b][hw][c]   16.8 MB
__device__ float g_woffT2[KK * 18];         // [k][ch]      166 KB
__device__ float g_wdefW[KK * OO];          // [k][o]       2.36 MB
__device__ float g_mean[OO];
__device__ float g_scale[OO];

// ---- packed f32x2 helpers ----
#define FMA2(d,a,b,c)  asm("fma.rn.f32x2 %0,%1,%2,%3;" : "=l"(d) : "l"(a),"l"(b),"l"(c))
#define PACK2(d,lo,hi) asm("mov.b64 %0,{%1,%2};" : "=l"(d) : "f"(lo),"f"(hi))
#define UNPACK2(lo,hi,s) asm("mov.b64 {%0,%1},%2;" : "=f"(lo),"=f"(hi) : "l"(s))
#define LDSV2(a,b,addr) asm volatile("ld.shared.v2.u64 {%0,%1},[%2];" : "=l"(a),"=l"(b) : "r"(addr))

// ---------------------------------------------------------------------------
// transpose x [B][C][HW] -> xT [B][HW][C]
// ---------------------------------------------------------------------------
__global__ void k_transpose_x(const float* __restrict__ x) {
    __shared__ float tile[32][33];
    int b   = blockIdx.z;
    int hw0 = blockIdx.x * 32;
    int c0  = blockIdx.y * 32;
    tile[threadIdx.y][threadIdx.x] =
        x[(b * CC + c0 + threadIdx.y) * 4096 + hw0 + threadIdx.x];
    __syncthreads();
    g_xT[(b * 4096 + hw0 + threadIdx.y) * CC + c0 + threadIdx.x] =
        tile[threadIdx.x][threadIdx.y];
}

// ---------------------------------------------------------------------------
// transpose w_off [ch][c][tap] -> g_woffT2[(tap*256+c)*18 + ch]
// ---------------------------------------------------------------------------
__global__ void k_transpose_woff(const float* __restrict__ w_off) {
    int idx = blockIdx.x * blockDim.x + threadIdx.x;
    if (idx >= 18 * CC * 9) return;
    int ch  = idx / (CC * 9);
    int r   = idx % (CC * 9);
    int c   = r / 9;
    int tap = r % 9;
    g_woffT2[(tap * CC + c) * 18 + ch] = w_off[idx];
}

// ---------------------------------------------------------------------------
// transpose w_def [o][c][k2] -> g_wdefW[(k2*256+c)*256 + o]
// ---------------------------------------------------------------------------
__global__ void k_transpose_wdef(const float* __restrict__ w_def) {
    int idx = blockIdx.x * blockDim.x + threadIdx.x;
    if (idx >= OO * KK) return;
    int o = idx & 255;
    int k = idx >> 8;            // k = k2*256 + c
    int c = k & 255;
    int k2 = k >> 8;
    g_wdefW[idx] = w_def[o * KK + c * 9 + k2];
}

// ---------------------------------------------------------------------------
// Fused main kernel. 256 threads, 32 px/block.
// smem floats: sv 16384 (GEMM layout: 256 rows x 16 slots x 16B, value-dup,
//   slot pos XOR-swizzled by c&15; offset phase reuses as [px][ROW])
//   | sw/spart 4608 | soff2 2304  -> 23296 floats = 93184 B, 2 CTAs/SM
// ---------------------------------------------------------------------------
__global__ void __launch_bounds__(256, 2)
k_main(float* __restrict__ out, const float* __restrict__ b_off) {
    extern __shared__ float sm[];
    float* sv    = sm;                  // 16384 floats
    float* sw    = sm + 16384;          // 4608 floats (aliased by spart)
    float* soff2 = sm + 20992;          // 2304 floats

    const int t    = threadIdx.x;
    const int pid0 = blockIdx.x * PT;
    const int b    = pid0 >> 12;
    const int hw0  = pid0 & 4095;
    const int h    = hw0 >> 6;
    const int w0   = hw0 & 63;
    const float* xb  = g_xT + ((size_t)b << 20);
    const char*  xbt = (const char*)xb + (t << 2);

    // ================= Offset conv (R3/R4-validated, b64 weight loads) =====
    unsigned long long oacc[9];
    #pragma unroll
    for (int j = 0; j < 9; j++) oacc[j] = 0ULL;
    const int opx = t >> 3, osl = t & 7;

    for (int tap = 0; tap < 9; tap++) {
        int y  = h + tap / 3 - 1;
        int kx = tap % 3 - 1;
        bool yok = (unsigned)y < 64u;
        #pragma unroll 8
        for (int px = 0; px < 32; px++) {
            int xx = w0 + px + kx;
            float v = 0.f;
            if (yok && (unsigned)xx < 64u) v = xb[(((y << 6) + xx) << 8) + t];
            sv[px * ROW + t] = v;
        }
        const float* gsrc = g_woffT2 + tap * 4608;
        #pragma unroll
        for (int i = 0; i < 18; i++) sw[i * 256 + t] = gsrc[i * 256 + t];
        __syncthreads();
        for (int i = 0; i < 32; i++) {
            int c = (i << 3) + osl;
            float sval = sv[opx * ROW + c];
            unsigned long long sp; PACK2(sp, sval, sval);
            const unsigned long long* swc =
                (const unsigned long long*)(sw + c * 18);
            #pragma unroll
            for (int j = 0; j < 9; j++)
                FMA2(oacc[j], sp, swc[j], oacc[j]);
        }
        __syncthreads();
    }

    {   // reduce k-slices -> offsets -> gather descriptors
        float* spart = sw;
        #pragma unroll
        for (int j = 0; j < 9; j++) {
            float lo, hi; UNPACK2(lo, hi, oacc[j]);
            spart[(((opx << 3) + osl) * 9 + j) * 2 + 0] = lo;
            spart[(((opx << 3) + osl) * 9 + j) * 2 + 1] = hi;
        }
        __syncthreads();
        for (int idx = t; idx < 288; idx += 256) {
            int px = idx / 9, j = idx - px * 9;
            float dy = b_off[2 * j], dx = b_off[2 * j + 1];
            #pragma unroll
            for (int s = 0; s < 8; s++) {
                dy += spart[(((px << 3) + s) * 9 + j) * 2 + 0];
                dx += spart[(((px << 3) + s) * 9 + j) * 2 + 1];
            }
            float py  = dy + (float)(j / 3) + (float)(h - 1);
            float pxf = dx + (float)(j % 3) + (float)(w0 + px - 1);
            float y0f = floorf(py),  x0f = floorf(pxf);
            float wy1 = py - y0f,    wx1 = pxf - x0f;
            float wy0 = 1.f - wy1,   wx0 = 1.f - wx1;
            float vy0 = (y0f >= 0.f  && y0f <= 63.f) ? 1.f : 0.f;
            float vy1 = (y0f >= -1.f && y0f <= 62.f) ? 1.f : 0.f;
            float vx0 = (x0f >= 0.f  && x0f <= 63.f) ? 1.f : 0.f;
            float vx1 = (x0f >= -1.f && x0f <= 62.f) ? 1.f : 0.f;
            int y0 = min(max((int)y0f, 0), 63);
            int x0 = min(max((int)x0f, 0), 63);
            int y1 = min(max((int)y0f + 1, 0), 63);
            int x1 = min(max((int)x0f + 1, 0), 63);
            float4 wq = make_float4(wy0 * wx0 * vy0 * vx0, wy0 * wx1 * vy0 * vx1,
                                    wy1 * wx0 * vy1 * vx0, wy1 * wx1 * vy1 * vx1);
            int4 oq = make_int4((((y0 << 6) + x0) << 10), (((y0 << 6) + x1) << 10),
                                (((y1 << 6) + x0) << 10), (((y1 << 6) + x1) << 10));
            *(float4*)(soff2 + idx * 8)     = wq;
            *(int4*)  (soff2 + idx * 8 + 4) = oq;
        }
        __syncthreads();
    }

    // ================= Main GEMM =================
    // thread: pxg = t&7 (4 px: 4*pxg..+3), og = t>>3 (8 o: og*8..+7)
    const int pxg = t & 7;
    const int og  = t >> 3;

    unsigned long long acc[16];     // [p*4 + i]: px p, o-pair i
    #pragma unroll
    for (int i = 0; i < 16; i++) acc[i] = 0ULL;

    unsigned svb = (unsigned)__cvta_generic_to_shared(sv);
    char* svc = (char*)sv;
    const int m15 = t & 15;

    for (int tap = 0; tap < 9; tap++) {
        // ---- gather into dup-swizzled sv: row c (=t), slot s at pos s^m15 ----
        #pragma unroll 2
        for (int q = 0; q < 8; q++) {
            float v[4];
            #pragma unroll
            for (int e = 0; e < 4; e++) {
                int idx = (q * 4 + e) * 9 + tap;
                float4 wq = *(const float4*)(soff2 + idx * 8);
                int4   oq = *(const int4*)  (soff2 + idx * 8 + 4);
                float vv;
                vv  = wq.x * *(const float*)(xbt + oq.x);
                vv += wq.y * *(const float*)(xbt + oq.y);
                vv += wq.z * *(const float*)(xbt + oq.z);
                vv += wq.w * *(const float*)(xbt + oq.w);
                v[e] = vv;
            }
            *(float4*)(svc + (t << 8) + ((( (2*q)   ^ m15) & 15) << 4)) =
                make_float4(v[0], v[0], v[1], v[1]);
            *(float4*)(svc + (t << 8) + ((( (2*q+1) ^ m15) & 15) << 4)) =
                make_float4(v[2], v[2], v[3], v[3]);
        }
        __syncthreads();

        // ---- GEMM over this tap's 256 k ----
        const float* wt = g_wdefW + (size_t)(tap * 256) * 256 + og * 8;
        ulonglong2 wA = *(const ulonglong2*)(wt);        // o pairs 01,23
        ulonglong2 wB = *(const ulonglong2*)(wt + 4);    // o pairs 45,67
        #pragma unroll 1
        for (int c8 = 0; c8 < 256; c8 += 8) {
            unsigned P    = (unsigned)(pxg ^ ((c8 >> 1) & 4));  // pxg ^ 4b
            unsigned rowb = svb + (unsigned)(c8 << 8);
            #pragma unroll
            for (int j = 0; j < 8; j++) {
                int cn = c8 + j + 1; if (cn > 255) cn = 255;
                ulonglong2 nA = *(const ulonglong2*)(wt + cn * 256);
                ulonglong2 nB = *(const ulonglong2*)(wt + cn * 256 + 4);
                unsigned a = rowb + (unsigned)(j << 8)
                           + (((P ^ (unsigned)(j >> 1)) & 7u) << 5);
                unsigned long long p0, p1, q0, q1;
                LDSV2(p0, p1, a);
                LDSV2(q0, q1, a + 16);
                unsigned long long sd0 = (j & 1) ? q0 : p0;  // px0
                unsigned long long sd1 = (j & 1) ? q1 : p1;  // px1
                unsigned long long sd2 = (j & 1) ? p0 : q0;  // px2
                unsigned long long sd3 = (j & 1) ? p1 : q1;  // px3
                FMA2(acc[0],  sd0, wA.x, acc[0]);
                FMA2(acc[1],  sd0, wA.y, acc[1]);
                FMA2(acc[2],  sd0, wB.x, acc[2]);
                FMA2(acc[3],  sd0, wB.y, acc[3]);
                FMA2(acc[4],  sd1, wA.x, acc[4]);
                FMA2(acc[5],  sd1, wA.y, acc[5]);
                FMA2(acc[6],  sd1, wB.x, acc[6]);
                FMA2(acc[7],  sd1, wB.y, acc[7]);
                FMA2(acc[8],  sd2, wA.x, acc[8]);
                FMA2(acc[9],  sd2, wA.y, acc[9]);
                FMA2(acc[10], sd2, wB.x, acc[10]);
                FMA2(acc[11], sd2, wB.y, acc[11]);
                FMA2(acc[12], sd3, wA.x, acc[12]);
                FMA2(acc[13], sd3, wA.y, acc[13]);
                FMA2(acc[14], sd3, wB.x, acc[14]);
                FMA2(acc[15], sd3, wB.y, acc[15]);
                wA = nA; wB = nB;
            }
        }
        __syncthreads();
    }

    // ---- store pre-BN result: 4 px x 8 o per thread ----
    #pragma unroll
    for (int i = 0; i < 4; i++) {
        float e0, o0, e1, o1, e2, o2, e3, o3;
        UNPACK2(e0, o0, acc[0 * 4 + i]);
        UNPACK2(e1, o1, acc[1 * 4 + i]);
        UNPACK2(e2, o2, acc[2 * 4 + i]);
        UNPACK2(e3, o3, acc[3 * 4 + i]);
        int oe = og * 8 + 2 * i;
        float* pe = out + (((size_t)((b << 8) + oe))     << 12) + hw0 + 4 * pxg;
        float* po = out + (((size_t)((b << 8) + oe + 1)) << 12) + hw0 + 4 * pxg;
        *(float4*)pe = make_float4(e0, e1, e2, e3);
        *(float4*)po = make_float4(o0, o1, o2, o3);
    }
}

// ---------------------------------------------------------------------------
// per-channel mean / inv-std
// ---------------------------------------------------------------------------
__global__ void k_stats(const float* __restrict__ out,
                        const float* __restrict__ gamma) {
    int o = blockIdx.x;
    int t = threadIdx.x, lane = t & 31, warp = t >> 5;
    float s = 0.f, s2 = 0.f;
    for (int b = 0; b < BB; b++) {
        const float4* p = (const float4*)(out + (((size_t)((b << 8) + o)) << 12));
        for (int i = t; i < 1024; i += 256) {
            float4 v = p[i];
            s += v.x + v.y + v.z + v.w;
            s2 = fmaf(v.x, v.x, s2); s2 = fmaf(v.y, v.y, s2);
            s2 = fmaf(v.z, v.z, s2); s2 = fmaf(v.w, v.w, s2);
        }
    }
    #pragma unroll
    for (int sft = 16; sft > 0; sft >>= 1) {
        s  += __shfl_xor_sync(0xffffffffu, s,  sft);
        s2 += __shfl_xor_sync(0xffffffffu, s2, sft);
    }
    __shared__ float rs[8], rs2[8];
    if (lane == 0) { rs[warp] = s; rs2[warp] = s2; }
    __syncthreads();
    if (t == 0) {
        float S = 0.f, S2 = 0.f;
        #pragma unroll
        for (int i = 0; i < 8; i++) { S += rs[i]; S2 += rs2[i]; }
        float mean = S * (1.f / 16384.f);
        float var  = S2 * (1.f / 16384.f) - mean * mean;
        g_mean[o]  = mean;
        g_scale[o] = gamma[o] * rsqrtf(var + 1e-5f);
    }
}

// ---------------------------------------------------------------------------
// in-place normalize + relu (float4)
// ---------------------------------------------------------------------------
__global__ void k_norm(float* __restrict__ out,
                       const float* __restrict__ beta) {
    int i4 = blockIdx.x * blockDim.x + threadIdx.x;
    if (i4 >= BB * OO * 1024) return;
    int o = (i4 >> 10) & 255;
    float mu = g_mean[o], sc = g_scale[o], be = beta[o];
    float4 v = ((float4*)out)[i4];
    v.x = fmaxf(fmaf(v.x - mu, sc, be), 0.f);
    v.y = fmaxf(fmaf(v.y - mu, sc, be), 0.f);
    v.z = fmaxf(fmaf(v.z - mu, sc, be), 0.f);
    v.w = fmaxf(fmaf(v.w - mu, sc, be), 0.f);
    ((float4*)out)[i4] = v;
}

// ---------------------------------------------------------------------------
extern "C" void kernel_launch(void* const* d_in, const int* in_sizes, int n_in,
                              void* d_out, int out_size) {
    const float* x     = (const float*)d_in[0];
    const float* w_off = (const float*)d_in[1];
    const float* b_off = (const float*)d_in[2];
    const float* w_def = (const float*)d_in[3];
    const float* gamma = (const float*)d_in[4];
    const float* beta  = (const float*)d_in[5];
    float* out = (float*)d_out;

    cudaFuncSetAttribute(k_main, cudaFuncAttributeMaxDynamicSharedMemorySize,
                         23296 * (int)sizeof(float));

    {
        dim3 grid(4096 / 32, CC / 32, BB), blk(32, 32);
        k_transpose_x<<<grid, blk>>>(x);
    }
    k_transpose_woff<<<(18 * CC * 9 + 255) / 256, 256>>>(w_off);
    k_transpose_wdef<<<(OO * KK + 255) / 256, 256>>>(w_def);

    k_main<<<NPIX / PT, 256, 23296 * sizeof(float)>>>(out, b_off);

    k_stats<<<OO, 256>>>(out, gamma);
    k_norm<<<(BB * OO * 1024 + 255) / 256, 256>>>(out, beta);
}

// round 6
// speedup vs baseline: 1.8932x; 1.8932x over previous
#include <cuda_runtime.h>
#include <math.h>

#define BB 4
#define CC 256
#define OO 256
#define KK 2304          // C * 9
#define NPIX 16384
#define PT 32            // pixels per block (one row segment, same h, same b)
#define ROW 260          // offset-phase sv row stride (floats)

// smem float layout: sv 0..8320 | wbuf/sw 8320..16512 | soff2 16512..18816
#define SM_WBUF 8320
#define SM_SOFF 16512
#define SM_TOTF 18816

// Static device scratch
__device__ float g_xT[BB * 4096 * CC];      // [b][hw][c]   16.8 MB
__device__ float g_woffT2[KK * 18];         // [k][ch]      166 KB
__device__ float g_wdefW[KK * OO];          // [k][o]       2.36 MB
__device__ float g_mean[OO];
__device__ float g_scale[OO];

// ---- packed f32x2 helpers ----
#define FMA2(d,a,b,c)  asm("fma.rn.f32x2 %0,%1,%2,%3;" : "=l"(d) : "l"(a),"l"(b),"l"(c))
#define PACK2(d,lo,hi) asm("mov.b64 %0,{%1,%2};" : "=l"(d) : "f"(lo),"f"(hi))
#define UNPACK2(lo,hi,s) asm("mov.b64 {%0,%1},%2;" : "=f"(lo),"=f"(hi) : "l"(s))
#define LDS128F(s,addr) asm volatile("ld.shared.v4.f32 {%0,%1,%2,%3},[%4];" \
    : "=f"(s.x),"=f"(s.y),"=f"(s.z),"=f"(s.w) : "r"(addr))
#define CPASYNC16(dst,src) asm volatile( \
    "cp.async.cg.shared.global [%0],[%1],16;" :: "r"(dst), "l"(src))
#define CPCOMMIT() asm volatile("cp.async.commit_group;" ::: "memory")
#define CPWAIT0()  asm volatile("cp.async.wait_group 0;" ::: "memory")

// ---------------------------------------------------------------------------
// transpose x [B][C][HW] -> xT [B][HW][C]
// ---------------------------------------------------------------------------
__global__ void k_transpose_x(const float* __restrict__ x) {
    __shared__ float tile[32][33];
    int b   = blockIdx.z;
    int hw0 = blockIdx.x * 32;
    int c0  = blockIdx.y * 32;
    tile[threadIdx.y][threadIdx.x] =
        x[(b * CC + c0 + threadIdx.y) * 4096 + hw0 + threadIdx.x];
    __syncthreads();
    g_xT[(b * 4096 + hw0 + threadIdx.y) * CC + c0 + threadIdx.x] =
        tile[threadIdx.x][threadIdx.y];
}

// ---------------------------------------------------------------------------
// transpose w_off [ch][c][tap] -> g_woffT2[(tap*256+c)*18 + ch]
// ---------------------------------------------------------------------------
__global__ void k_transpose_woff(const float* __restrict__ w_off) {
    int idx = blockIdx.x * blockDim.x + threadIdx.x;
    if (idx >= 18 * CC * 9) return;
    int ch  = idx / (CC * 9);
    int r   = idx % (CC * 9);
    int c   = r / 9;
    int tap = r % 9;
    g_woffT2[(tap * CC + c) * 18 + ch] = w_off[idx];
}

// ---------------------------------------------------------------------------
// transpose w_def [o][c][k2] -> g_wdefW[(k2*256+c)*256 + o]
// ---------------------------------------------------------------------------
__global__ void k_transpose_wdef(const float* __restrict__ w_def) {
    int idx = blockIdx.x * blockDim.x + threadIdx.x;
    if (idx >= OO * KK) return;
    int o = idx & 255;
    int k = idx >> 8;            // k = k2*256 + c
    int c = k & 255;
    int k2 = k >> 8;
    g_wdefW[idx] = w_def[o * KK + c * 9 + k2];
}

// ---------------------------------------------------------------------------
// Fused main kernel (R4 body + cp.async double-buffered weight tiles).
// 256 threads, 32 px/block.  smem 75264 B -> 2 CTAs/SM.
// ---------------------------------------------------------------------------
__global__ void __launch_bounds__(256, 2)
k_main(float* __restrict__ out, const float* __restrict__ b_off) {
    extern __shared__ float sm[];
    float* sv    = sm;                  // 8320 floats (both layouts)
    float* sw    = sm + SM_WBUF;        // offset phase weights / GEMM wbuf
    float* soff2 = sm + SM_SOFF;        // 2304 floats

    const int t    = threadIdx.x;
    const int pid0 = blockIdx.x * PT;
    const int b    = pid0 >> 12;
    const int hw0  = pid0 & 4095;
    const int h    = hw0 >> 6;
    const int w0   = hw0 & 63;
    const float* xb  = g_xT + ((size_t)b << 20);
    const char*  xbt = (const char*)xb + (t << 2);

    // ================= Offset conv (R4-validated) =================
    unsigned long long oacc[9];
    #pragma unroll
    for (int j = 0; j < 9; j++) oacc[j] = 0ULL;
    const int opx = t >> 3, osl = t & 7;

    for (int tap = 0; tap < 9; tap++) {
        int y  = h + tap / 3 - 1;
        int kx = tap % 3 - 1;
        bool yok = (unsigned)y < 64u;
        #pragma unroll 8
        for (int px = 0; px < 32; px++) {
            int xx = w0 + px + kx;
            float v = 0.f;
            if (yok && (unsigned)xx < 64u) v = xb[(((y << 6) + xx) << 8) + t];
            sv[px * ROW + t] = v;
        }
        const float* gsrc = g_woffT2 + tap * 4608;
        #pragma unroll
        for (int i = 0; i < 18; i++) sw[i * 256 + t] = gsrc[i * 256 + t];
        __syncthreads();
        for (int i = 0; i < 32; i++) {
            int c = (i << 3) + osl;
            float sval = sv[opx * ROW + c];
            unsigned long long sp; PACK2(sp, sval, sval);
            const unsigned long long* swc =
                (const unsigned long long*)(sw + c * 18);
            #pragma unroll
            for (int j = 0; j < 9; j++)
                FMA2(oacc[j], sp, swc[j], oacc[j]);
        }
        __syncthreads();
    }

    {   // reduce k-slices -> offsets -> gather descriptors
        float* spart = sw;
        #pragma unroll
        for (int j = 0; j < 9; j++) {
            float lo, hi; UNPACK2(lo, hi, oacc[j]);
            spart[(((opx << 3) + osl) * 9 + j) * 2 + 0] = lo;
            spart[(((opx << 3) + osl) * 9 + j) * 2 + 1] = hi;
        }
        __syncthreads();
        for (int idx = t; idx < 288; idx += 256) {
            int px = idx / 9, j = idx - px * 9;
            float dy = b_off[2 * j], dx = b_off[2 * j + 1];
            #pragma unroll
            for (int s = 0; s < 8; s++) {
                dy += spart[(((px << 3) + s) * 9 + j) * 2 + 0];
                dx += spart[(((px << 3) + s) * 9 + j) * 2 + 1];
            }
            float py  = dy + (float)(j / 3) + (float)(h - 1);
            float pxf = dx + (float)(j % 3) + (float)(w0 + px - 1);
            float y0f = floorf(py),  x0f = floorf(pxf);
            float wy1 = py - y0f,    wx1 = pxf - x0f;
            float wy0 = 1.f - wy1,   wx0 = 1.f - wx1;
            float vy0 = (y0f >= 0.f  && y0f <= 63.f) ? 1.f : 0.f;
            float vy1 = (y0f >= -1.f && y0f <= 62.f) ? 1.f : 0.f;
            float vx0 = (x0f >= 0.f  && x0f <= 63.f) ? 1.f : 0.f;
            float vx1 = (x0f >= -1.f && x0f <= 62.f) ? 1.f : 0.f;
            int y0 = min(max((int)y0f, 0), 63);
            int x0 = min(max((int)x0f, 0), 63);
            int y1 = min(max((int)y0f + 1, 0), 63);
            int x1 = min(max((int)x0f + 1, 0), 63);
            float4 wq = make_float4(wy0 * wx0 * vy0 * vx0, wy0 * wx1 * vy0 * vx1,
                                    wy1 * wx0 * vy1 * vx0, wy1 * wx1 * vy1 * vx1);
            int4 oq = make_int4((((y0 << 6) + x0) << 10), (((y0 << 6) + x1) << 10),
                                (((y1 << 6) + x0) << 10), (((y1 << 6) + x1) << 10));
            *(float4*)(soff2 + idx * 8)     = wq;
            *(int4*)  (soff2 + idx * 8 + 4) = oq;
        }
        __syncthreads();
    }

    // ================= Main GEMM (R4 mapping, smem-staged weights) =========
    const int pxq = t & 7;
    const int og  = (t & 31) >> 3;
    const int wo  = ((t >> 5) << 5) + (og << 3);    // base output channel

    unsigned long long acc[16];
    #pragma unroll
    for (int i = 0; i < 16; i++) acc[i] = 0ULL;

    unsigned svb = (unsigned)__cvta_generic_to_shared(sv);
    unsigned wsb = (unsigned)__cvta_generic_to_shared(sw);
    char* svc = (char*)sv;
    const int woB = (t & 31) >> 3 ? 0 : 0;  // (placeholder, wo used below)
    const unsigned wthr = (unsigned)(((t & 31) >> 3) * 32 + ((t >> 5) << 7));
    // NOTE: weight row layout [k][256 o]; this thread reads o = wo..wo+7
    //       at byte offset wo*4 within the 1024-B k-row.

    for (int tap = 0; tap < 9; tap++) {
        // ---- gather into sv[c=t][px] with tile-of-4 xor swizzle ----
        #pragma unroll 2
        for (int q = 0; q < 8; q++) {
            float v[4];
            #pragma unroll
            for (int e = 0; e < 4; e++) {
                int idx = (q * 4 + e) * 9 + tap;
                float4 wq = *(const float4*)(soff2 + idx * 8);
                int4   oq = *(const int4*)  (soff2 + idx * 8 + 4);
                float vv;
                vv  = wq.x * *(const float*)(xbt + oq.x);
                vv += wq.y * *(const float*)(xbt + oq.y);
                vv += wq.z * *(const float*)(xbt + oq.z);
                vv += wq.w * *(const float*)(xbt + oq.w);
                v[e] = vv;
            }
            *(float4*)(svc + (t << 7) + (((q ^ t) & 7) << 4)) =
                make_float4(v[0], v[1], v[2], v[3]);
        }
        __syncthreads();

        // ---- prologue: async-load weight tile 0 of this tap ----
        const char* gw = (const char*)(g_wdefW + (size_t)(tap * 256) * 256);
        {
            unsigned dst = wsb + (unsigned)(t << 4);
            const char* src = gw + (t << 4);
            #pragma unroll
            for (int u = 0; u < 4; u++)
                CPASYNC16(dst + u * 4096, src + u * 4096);
            CPCOMMIT();
        }

        // ---- 16 tiles x 16 k ----
        for (int ti = 0; ti < 16; ti++) {
            CPWAIT0();
            __syncthreads();
            if (ti + 1 < 16) {
                unsigned dst = wsb + (unsigned)(((ti + 1) & 1) * 16384 + (t << 4));
                const char* src = gw + (ti + 1) * 16384 + (t << 4);
                #pragma unroll
                for (int u = 0; u < 4; u++)
                    CPASYNC16(dst + u * 4096, src + u * 4096);
                CPCOMMIT();
            }
            const float* wst = sw + (ti & 1) * 4096 + wo;   // k-row 0 of tile
            unsigned svrow = svb + (unsigned)((ti * 16) << 7);
            #pragma unroll
            for (int j = 0; j < 16; j++) {
                float4 s;
                unsigned a = svrow + (unsigned)(j << 7)
                           + (((unsigned)(pxq ^ j) & 7u) << 4);
                LDS128F(s, a);
                const unsigned long long* wp =
                    (const unsigned long long*)(wst + j * 256);
                unsigned long long w0v = wp[0], w1v = wp[1],
                                   w2v = wp[2], w3v = wp[3];
                unsigned long long sd0, sd1, sd2, sd3;
                PACK2(sd0, s.x, s.x); PACK2(sd1, s.y, s.y);
                PACK2(sd2, s.z, s.z); PACK2(sd3, s.w, s.w);
                FMA2(acc[0],  sd0, w0v, acc[0]);  FMA2(acc[1],  sd0, w1v, acc[1]);
                FMA2(acc[2],  sd0, w2v, acc[2]);  FMA2(acc[3],  sd0, w3v, acc[3]);
                FMA2(acc[4],  sd1, w0v, acc[4]);  FMA2(acc[5],  sd1, w1v, acc[5]);
                FMA2(acc[6],  sd1, w2v, acc[6]);  FMA2(acc[7],  sd1, w3v, acc[7]);
                FMA2(acc[8],  sd2, w0v, acc[8]);  FMA2(acc[9],  sd2, w1v, acc[9]);
                FMA2(acc[10], sd2, w2v, acc[10]); FMA2(acc[11], sd2, w3v, acc[11]);
                FMA2(acc[12], sd3, w0v, acc[12]); FMA2(acc[13], sd3, w1v, acc[13]);
                FMA2(acc[14], sd3, w2v, acc[14]); FMA2(acc[15], sd3, w3v, acc[15]);
            }
        }
        __syncthreads();
    }

    // ---- store pre-BN result: 4 px x 8 o per thread ----
    #pragma unroll
    for (int op = 0; op < 4; op++) {
        float l0, h0, l1, h1, l2, h2, l3, h3;
        UNPACK2(l0, h0, acc[0 * 4 + op]);
        UNPACK2(l1, h1, acc[1 * 4 + op]);
        UNPACK2(l2, h2, acc[2 * 4 + op]);
        UNPACK2(l3, h3, acc[3 * 4 + op]);
        int oe = wo + 2 * op;
        float* pe = out + (((size_t)((b << 8) + oe))     << 12) + hw0 + (pxq << 2);
        float* po = out + (((size_t)((b << 8) + oe + 1)) << 12) + hw0 + (pxq << 2);
        *(float4*)pe = make_float4(l0, l1, l2, l3);
        *(float4*)po = make_float4(h0, h1, h2, h3);
    }
}

// ---------------------------------------------------------------------------
// per-channel mean / inv-std
// ---------------------------------------------------------------------------
__global__ void k_stats(const float* __restrict__ out,
                        const float* __restrict__ gamma) {
    int o = blockIdx.x;
    int t = threadIdx.x, lane = t & 31, warp = t >> 5;
    float s = 0.f, s2 = 0.f;
    for (int b = 0; b < BB; b++) {
        const float4* p = (const float4*)(out + (((size_t)((b << 8) + o)) << 12));
        for (int i = t; i < 1024; i += 256) {
            float4 v = p[i];
            s += v.x + v.y + v.z + v.w;
            s2 = fmaf(v.x, v.x, s2); s2 = fmaf(v.y, v.y, s2);
            s2 = fmaf(v.z, v.z, s2); s2 = fmaf(v.w, v.w, s2);
        }
    }
    #pragma unroll
    for (int sft = 16; sft > 0; sft >>= 1) {
        s  += __shfl_xor_sync(0xffffffffu, s,  sft);
        s2 += __shfl_xor_sync(0xffffffffu, s2, sft);
    }
    __shared__ float rs[8], rs2[8];
    if (lane == 0) { rs[warp] = s; rs2[warp] = s2; }
    __syncthreads();
    if (t == 0) {
        float S = 0.f, S2 = 0.f;
        #pragma unroll
        for (int i = 0; i < 8; i++) { S += rs[i]; S2 += rs2[i]; }
        float mean = S * (1.f / 16384.f);
        float var  = S2 * (1.f / 16384.f) - mean * mean;
        g_mean[o]  = mean;
        g_scale[o] = gamma[o] * rsqrtf(var + 1e-5f);
    }
}

// ---------------------------------------------------------------------------
// in-place normalize + relu (float4)
// ---------------------------------------------------------------------------
__global__ void k_norm(float* __restrict__ out,
                       const float* __restrict__ beta) {
    int i4 = blockIdx.x * blockDim.x + threadIdx.x;
    if (i4 >= BB * OO * 1024) return;
    int o = (i4 >> 10) & 255;
    float mu = g_mean[o], sc = g_scale[o], be = beta[o];
    float4 v = ((float4*)out)[i4];
    v.x = fmaxf(fmaf(v.x - mu, sc, be), 0.f);
    v.y = fmaxf(fmaf(v.y - mu, sc, be), 0.f);
    v.z = fmaxf(fmaf(v.z - mu, sc, be), 0.f);
    v.w = fmaxf(fmaf(v.w - mu, sc, be), 0.f);
    ((float4*)out)[i4] = v;
}

// ---------------------------------------------------------------------------
extern "C" void kernel_launch(void* const* d_in, const int* in_sizes, int n_in,
                              void* d_out, int out_size) {
    const float* x     = (const float*)d_in[0];
    const float* w_off = (const float*)d_in[1];
    const float* b_off = (const float*)d_in[2];
    const float* w_def = (const float*)d_in[3];
    const float* gamma = (const float*)d_in[4];
    const float* beta  = (const float*)d_in[5];
    float* out = (float*)d_out;

    cudaFuncSetAttribute(k_main, cudaFuncAttributeMaxDynamicSharedMemorySize,
                         SM_TOTF * (int)sizeof(float));

    {
        dim3 grid(4096 / 32, CC / 32, BB), blk(32, 32);
        k_transpose_x<<<grid, blk>>>(x);
    }
    k_transpose_woff<<<(18 * CC * 9 + 255) / 256, 256>>>(w_off);
    k_transpose_wdef<<<(OO * KK + 255) / 256, 256>>>(w_def);

    k_main<<<NPIX / PT, 256, SM_TOTF * sizeof(float)>>>(out, b_off);

    k_stats<<<OO, 256>>>(out, gamma);
    k_norm<<<(BB * OO * 1024 + 255) / 256, 256>>>(out, beta);
}